// round 5
// baseline (speedup 1.0000x reference)
#include <cuda_runtime.h>
#include <cstdint>

#define N_NODES 100000
#define FDIM 512
#define HDIM 64

// ---------------- scratch (device globals; 128B-aligned for vector access) ----------------
__device__ __align__(128) float g_x1s[(size_t)N_NODES * HDIM];   // (X@W1) * norm_src
__device__ __align__(128) float g_agg[(size_t)N_NODES * HDIM];   // layer-1 aggregation
__device__ __align__(128) float g_hs[(size_t)N_NODES * HDIM];    // relu(agg*nd)*ns
__device__ __align__(128) float g_agg2[(size_t)N_NODES * HDIM];  // layer-2 aggregation
__device__ __align__(128) float g_deg_out[N_NODES];
__device__ __align__(128) float g_deg_in[N_NODES];
__device__ __align__(128) float g_norm_src[N_NODES];
__device__ __align__(128) float g_norm_dst[N_NODES];
__device__ int g_is64;  // 1 if index arrays are int64, 0 if int32

// ---------------- index width probe (deterministic) ----------------
// If indices are int64 (values < 2^31), every odd 32-bit word is 0.
__global__ void detect_kernel(const int* __restrict__ src32,
                              const int* __restrict__ dst32, int E) {
    if (threadIdx.x == 0 && blockIdx.x == 0) {
        int n = E < 256 ? E : 256;
        int is64 = 1;
        for (int i = 0; i < n; i++) {
            if (src32[2 * i + 1] != 0 || dst32[2 * i + 1] != 0) { is64 = 0; break; }
        }
        g_is64 = is64;
    }
}

__device__ __forceinline__ int load_idx(const void* p, int e, int is64) {
    if (is64) return (int)__ldg(reinterpret_cast<const long long*>(p) + e);
    return __ldg(reinterpret_cast<const int*>(p) + e);
}

// ---------------- zero scratch ----------------
__global__ __launch_bounds__(256) void zero_kernel(int n) {
    int i = blockIdx.x * blockDim.x + threadIdx.x;
    int tot4 = n * (HDIM / 4);
    float4 z = make_float4(0.f, 0.f, 0.f, 0.f);
    if (i < tot4) {
        reinterpret_cast<float4*>(g_agg)[i] = z;
        reinterpret_cast<float4*>(g_agg2)[i] = z;
    }
    if (i < n) {
        g_deg_out[i] = 0.f;
        g_deg_in[i] = 0.f;
    }
}

// ---------------- degrees ----------------
__global__ __launch_bounds__(256) void degree_kernel(const void* __restrict__ src,
                                                     const void* __restrict__ dst,
                                                     int E) {
    int e = blockIdx.x * blockDim.x + threadIdx.x;
    if (e < E) {
        int is64 = g_is64;
        int s = load_idx(src, e, is64);
        int d = load_idx(dst, e, is64);
        atomicAdd(&g_deg_out[s], 1.0f);
        atomicAdd(&g_deg_in[d], 1.0f);
    }
}

// ---------------- norms ----------------
__global__ __launch_bounds__(256) void norm_kernel(int n) {
    int i = blockIdx.x * blockDim.x + threadIdx.x;
    if (i < n) {
        g_norm_src[i] = rsqrtf(fmaxf(g_deg_out[i], 1.0f));
        g_norm_dst[i] = rsqrtf(fmaxf(g_deg_in[i], 1.0f));
    }
}

// ---------------- SGEMM: C[M,N] = (rsA.*A)[M,K] @ B[K,N], C row-scaled by rsC ----------------
#define BM 64
#define BN 64
#define BK 32
__global__ __launch_bounds__(256) void sgemm_kernel(const float* __restrict__ A,
                                                    const float* __restrict__ B,
                                                    float* __restrict__ C,
                                                    int M, int N, int K,
                                                    const float* __restrict__ rsA,
                                                    const float* __restrict__ rsC) {
    __shared__ float As[BK][BM + 4];  // [k][m]
    __shared__ float Bs[BK][BN];      // [k][n]

    const int block_m = blockIdx.y * BM;
    const int block_n = blockIdx.x * BN;
    const int tid = threadIdx.x;
    const int tx = tid & 15;   // 0..15 -> n
    const int ty = tid >> 4;   // 0..15 -> m

    const int a_row = tid >> 3;          // 0..31
    const int a_col4 = (tid & 7) * 4;    // 0,4,...,28
    const int b_row = tid >> 4;          // 0..15
    const int b_col4 = (tid & 15) * 4;   // 0..60

    float acc[4][4];
#pragma unroll
    for (int i = 0; i < 4; i++)
#pragma unroll
        for (int j = 0; j < 4; j++) acc[i][j] = 0.f;

    for (int k0 = 0; k0 < K; k0 += BK) {
#pragma unroll
        for (int p = 0; p < 2; p++) {
            int r = block_m + a_row + p * 32;
            float4 v = make_float4(0.f, 0.f, 0.f, 0.f);
            if (r < M) {
                v = *reinterpret_cast<const float4*>(A + (size_t)r * K + k0 + a_col4);
                if (rsA) {
                    float s = __ldg(&rsA[r]);
                    v.x *= s; v.y *= s; v.z *= s; v.w *= s;
                }
            }
            int m = a_row + p * 32;
            As[a_col4 + 0][m] = v.x;
            As[a_col4 + 1][m] = v.y;
            As[a_col4 + 2][m] = v.z;
            As[a_col4 + 3][m] = v.w;
        }
#pragma unroll
        for (int p = 0; p < 2; p++) {
            int r = k0 + b_row + p * 16;
            float4 v = *reinterpret_cast<const float4*>(B + (size_t)r * N + block_n + b_col4);
            *reinterpret_cast<float4*>(&Bs[b_row + p * 16][b_col4]) = v;
        }
        __syncthreads();

#pragma unroll
        for (int kk = 0; kk < BK; kk++) {
            float4 a4 = *reinterpret_cast<const float4*>(&As[kk][ty * 4]);
            float4 b4 = *reinterpret_cast<const float4*>(&Bs[kk][tx * 4]);
            float a[4] = {a4.x, a4.y, a4.z, a4.w};
            float b[4] = {b4.x, b4.y, b4.z, b4.w};
#pragma unroll
            for (int i = 0; i < 4; i++)
#pragma unroll
                for (int j = 0; j < 4; j++) acc[i][j] = fmaf(a[i], b[j], acc[i][j]);
        }
        __syncthreads();
    }

#pragma unroll
    for (int i = 0; i < 4; i++) {
        int row = block_m + ty * 4 + i;
        if (row < M) {
            float s = rsC ? __ldg(&rsC[row]) : 1.0f;
            float4 o = make_float4(acc[i][0] * s, acc[i][1] * s, acc[i][2] * s, acc[i][3] * s);
            *reinterpret_cast<float4*>(C + (size_t)row * N + block_n + tx * 4) = o;
        }
    }
}

// ---------------- edge scatter: agg[dst] += msg[src] (64 floats/edge) ----------------
// 16 threads per edge; float4 gather + 4 scalar atomicAdds.
__global__ __launch_bounds__(256) void scatter64_kernel(const float* __restrict__ msg,
                                                        float* __restrict__ agg,
                                                        const void* __restrict__ src,
                                                        const void* __restrict__ dst,
                                                        int E) {
    int idx = blockIdx.x * blockDim.x + threadIdx.x;
    if (idx >= E * 16) return;
    int e = idx >> 4;
    int c = idx & 15;
    int is64 = g_is64;
    int s = load_idx(src, e, is64);
    int d = load_idx(dst, e, is64);
    float4 v = __ldg(reinterpret_cast<const float4*>(msg + (size_t)s * HDIM + c * 4));
    float* p = agg + (size_t)d * HDIM + c * 4;
    atomicAdd(p + 0, v.x);
    atomicAdd(p + 1, v.y);
    atomicAdd(p + 2, v.z);
    atomicAdd(p + 3, v.w);
}

// ---------------- h = relu(agg * norm_dst) * norm_src ----------------
__global__ __launch_bounds__(256) void h_kernel(int n) {
    int idx = blockIdx.x * blockDim.x + threadIdx.x;
    int tot4 = n * (HDIM / 4);
    if (idx >= tot4) return;
    int row = idx >> 4;
    float nd = g_norm_dst[row];
    float ns = g_norm_src[row];
    float4 v = reinterpret_cast<const float4*>(g_agg)[idx];
    float4 o;
    o.x = fmaxf(v.x * nd, 0.f) * ns;
    o.y = fmaxf(v.y * nd, 0.f) * ns;
    o.z = fmaxf(v.z * nd, 0.f) * ns;
    o.w = fmaxf(v.w * nd, 0.f) * ns;
    reinterpret_cast<float4*>(g_hs)[idx] = o;
}

// ---------------- launch ----------------
extern "C" void kernel_launch(void* const* d_in, const int* in_sizes, int n_in,
                              void* d_out, int out_size) {
    const float* features = (const float*)d_in[0];  // [N, 512]
    const void* src = d_in[1];                      // [E] int32 (or int64)
    const void* dst = d_in[2];                      // [E] int32 (or int64)
    const float* W1 = (const float*)d_in[3];        // [512, 64]
    const float* W2 = (const float*)d_in[4];        // [64, 512]
    float* out = (float*)d_out;                     // [N, 512]

    const int N = N_NODES;
    const int E = in_sizes[1];

    float *p_x1s, *p_agg, *p_hs, *p_agg2, *p_ns, *p_nd;
    cudaGetSymbolAddress((void**)&p_x1s, g_x1s);
    cudaGetSymbolAddress((void**)&p_agg, g_agg);
    cudaGetSymbolAddress((void**)&p_hs, g_hs);
    cudaGetSymbolAddress((void**)&p_agg2, g_agg2);
    cudaGetSymbolAddress((void**)&p_ns, g_norm_src);
    cudaGetSymbolAddress((void**)&p_nd, g_norm_dst);

    // 0) detect index width
    detect_kernel<<<1, 32>>>((const int*)src, (const int*)dst, E);
    // 1) zero
    {
        int tot = N * (HDIM / 4);
        zero_kernel<<<(tot + 255) / 256, 256>>>(N);
    }
    // 2) degrees
    degree_kernel<<<(E + 255) / 256, 256>>>(src, dst, E);
    // 3) norms
    norm_kernel<<<(N + 255) / 256, 256>>>(N);
    // 4) GEMM1: x1s = (X @ W1) * norm_src  [N,64]
    {
        dim3 grid(HDIM / BN, (N + BM - 1) / BM);
        sgemm_kernel<<<grid, 256>>>(features, W1, p_x1s, N, HDIM, FDIM, nullptr, p_ns);
    }
    // 5) edge scatter 1: agg[dst] += x1s[src]
    {
        int tot = E * 16;
        scatter64_kernel<<<(tot + 255) / 256, 256>>>(p_x1s, p_agg, src, dst, E);
    }
    // 6) h = relu(agg * norm_dst) * norm_src
    {
        int tot = N * (HDIM / 4);
        h_kernel<<<(tot + 255) / 256, 256>>>(N);
    }
    // 7) edge scatter 2: agg2[dst] += hs[src]
    {
        int tot = E * 16;
        scatter64_kernel<<<(tot + 255) / 256, 256>>>(p_hs, p_agg2, src, dst, E);
    }
    // 8) GEMM2: out = (agg2 * norm_dst) @ W2  [N,512]
    {
        dim3 grid(FDIM / BN, (N + BM - 1) / BM);
        sgemm_kernel<<<grid, 256>>>(p_agg2, W2, out, N, FDIM, HDIM, p_nd, nullptr);
    }
}

// round 6
// speedup vs baseline: 1.9023x; 1.9023x over previous
#include <cuda_runtime.h>
#include <cstdint>

#define N_NODES 100000
#define E_MAX   1600000
#define FDIM 512
#define HDIM 64

// ---------------- scratch ----------------
__device__ __align__(128) float g_x1s[(size_t)N_NODES * HDIM];   // (X@W1)*ns  (layer-1 messages)
__device__ __align__(128) float g_hs[(size_t)N_NODES * HDIM];    // relu(agg1*nd)*ns (layer-2 messages)
__device__ __align__(128) float g_agg2[(size_t)N_NODES * HDIM];  // (agg2*nd)
__device__ __align__(128) float g_norm_src[N_NODES];
__device__ __align__(128) float g_norm_dst[N_NODES];
__device__ int g_cnt_in[N_NODES];
__device__ int g_cnt_out[N_NODES];
__device__ int g_row_start[N_NODES + 1];
__device__ int g_cursor[N_NODES];
__device__ int g_esrc[E_MAX];    // src ids bucketed by dst
__device__ int g_bsum[256];
__device__ int g_is64;

// ---------------- index width probe ----------------
__global__ void detect_kernel(const int* __restrict__ src32,
                              const int* __restrict__ dst32, int E) {
    if (threadIdx.x == 0 && blockIdx.x == 0) {
        int n = E < 256 ? E : 256;
        int is64 = 1;
        for (int i = 0; i < n; i++) {
            if (src32[2 * i + 1] != 0 || dst32[2 * i + 1] != 0) { is64 = 0; break; }
        }
        g_is64 = is64;
    }
}

__device__ __forceinline__ int load_idx(const void* p, int e, int is64) {
    if (is64) return (int)__ldg(reinterpret_cast<const long long*>(p) + e);
    return __ldg(reinterpret_cast<const int*>(p) + e);
}

// ---------------- zero int counters ----------------
__global__ __launch_bounds__(256) void zero_counts_kernel(int n) {
    int i = blockIdx.x * blockDim.x + threadIdx.x;
    if (i < n) { g_cnt_in[i] = 0; g_cnt_out[i] = 0; }
}

// ---------------- degree histograms (int atomics) ----------------
__global__ __launch_bounds__(256) void hist_kernel(const void* __restrict__ src,
                                                   const void* __restrict__ dst, int E) {
    int e = blockIdx.x * blockDim.x + threadIdx.x;
    if (e < E) {
        int is64 = g_is64;
        atomicAdd(&g_cnt_out[load_idx(src, e, is64)], 1);
        atomicAdd(&g_cnt_in[load_idx(dst, e, is64)], 1);
    }
}

// ---------------- norms ----------------
__global__ __launch_bounds__(256) void norm_kernel(int n) {
    int i = blockIdx.x * blockDim.x + threadIdx.x;
    if (i < n) {
        g_norm_src[i] = rsqrtf(fmaxf((float)g_cnt_out[i], 1.0f));
        g_norm_dst[i] = rsqrtf(fmaxf((float)g_cnt_in[i], 1.0f));
    }
}

// ---------------- exclusive scan of g_cnt_in (3 phases) ----------------
__global__ __launch_bounds__(256) void scan1_kernel(int n) {
    __shared__ int sh[256];
    int tid = threadIdx.x;
    int base = blockIdx.x * 1024 + tid * 4;
    int v[4];
#pragma unroll
    for (int k = 0; k < 4; k++) v[k] = (base + k < n) ? g_cnt_in[base + k] : 0;
    int t = v[0] + v[1] + v[2] + v[3];
    sh[tid] = t;
    __syncthreads();
    for (int off = 1; off < 256; off <<= 1) {
        int x = (tid >= off) ? sh[tid - off] : 0;
        __syncthreads();
        sh[tid] += x;
        __syncthreads();
    }
    int run = sh[tid] - t;  // exclusive offset within block
#pragma unroll
    for (int k = 0; k < 4; k++) {
        if (base + k < n) g_row_start[base + k] = run;
        run += v[k];
    }
    if (tid == 255) g_bsum[blockIdx.x] = sh[255];
}

__global__ void scan2_kernel(int nb) {
    if (threadIdx.x == 0 && blockIdx.x == 0) {
        int running = 0;
        for (int b = 0; b < nb; b++) {
            int t = g_bsum[b];
            g_bsum[b] = running;
            running += t;
        }
    }
}

__global__ __launch_bounds__(256) void scan3_kernel(int n, int E) {
    int i = blockIdx.x * blockDim.x + threadIdx.x;
    if (i < n) {
        int v = g_row_start[i] + g_bsum[i >> 10];
        g_row_start[i] = v;
        g_cursor[i] = v;
    }
    if (i == 0) g_row_start[n] = E;
}

// ---------------- CSR fill: bucket src ids by dst ----------------
__global__ __launch_bounds__(256) void fill_kernel(const void* __restrict__ src,
                                                   const void* __restrict__ dst, int E) {
    int e = blockIdx.x * blockDim.x + threadIdx.x;
    if (e < E) {
        int is64 = g_is64;
        int s = load_idx(src, e, is64);
        int d = load_idx(dst, e, is64);
        int pos = atomicAdd(&g_cursor[d], 1);
        g_esrc[pos] = s;
    }
}

// ---------------- aggregation: out[node] = f(sum_{src in-edges} msg[src]) ----------------
// 16 threads per node, one float4 per thread; atomic-free, register accumulation.
// MODE 0: out = relu(sum*nd)*ns   MODE 1: out = sum*nd
template <int MODE>
__global__ __launch_bounds__(256) void agg_kernel(const float* __restrict__ msg,
                                                  float* __restrict__ outbuf, int n) {
    int node = blockIdx.x * 16 + (threadIdx.x >> 4);
    int c = threadIdx.x & 15;
    if (node >= n) return;
    int j = g_row_start[node];
    int s1 = g_row_start[node + 1];
    float4 acc = make_float4(0.f, 0.f, 0.f, 0.f);
    // 2-way unrolled gather (MLP=2); all 16 lanes of a node load the same
    // g_esrc word (single broadcast transaction).
    for (; j + 1 < s1; j += 2) {
        int sa = __ldg(&g_esrc[j]);
        int sb = __ldg(&g_esrc[j + 1]);
        float4 va = __ldg(reinterpret_cast<const float4*>(msg + (size_t)sa * HDIM + c * 4));
        float4 vb = __ldg(reinterpret_cast<const float4*>(msg + (size_t)sb * HDIM + c * 4));
        acc.x += va.x; acc.y += va.y; acc.z += va.z; acc.w += va.w;
        acc.x += vb.x; acc.y += vb.y; acc.z += vb.z; acc.w += vb.w;
    }
    if (j < s1) {
        int sa = __ldg(&g_esrc[j]);
        float4 va = __ldg(reinterpret_cast<const float4*>(msg + (size_t)sa * HDIM + c * 4));
        acc.x += va.x; acc.y += va.y; acc.z += va.z; acc.w += va.w;
    }
    float nd = g_norm_dst[node];
    float4 o;
    if (MODE == 0) {
        float ns = g_norm_src[node];
        o.x = fmaxf(acc.x * nd, 0.f) * ns;
        o.y = fmaxf(acc.y * nd, 0.f) * ns;
        o.z = fmaxf(acc.z * nd, 0.f) * ns;
        o.w = fmaxf(acc.w * nd, 0.f) * ns;
    } else {
        o.x = acc.x * nd; o.y = acc.y * nd; o.z = acc.z * nd; o.w = acc.w * nd;
    }
    reinterpret_cast<float4*>(outbuf)[(size_t)node * 16 + c] = o;
}

// ---------------- SGEMM: C[M,N] = (A)[M,K] @ B[K,N], C row-scaled by rsC ----------------
// BM=128, BN=64, BK=32, 256 threads, 8x4 per thread.
#define BM 128
#define BN 64
#define BK 32
__global__ __launch_bounds__(256) void sgemm_kernel(const float* __restrict__ A,
                                                    const float* __restrict__ B,
                                                    float* __restrict__ C,
                                                    int M, int N, int K,
                                                    const float* __restrict__ rsC) {
    __shared__ float As[BK][BM + 4];  // [k][m]
    __shared__ float Bs[BK][BN];      // [k][n]

    const int block_m = blockIdx.y * BM;
    const int block_n = blockIdx.x * BN;
    const int tid = threadIdx.x;
    const int tx = tid & 15;   // n: tx*4
    const int ty = tid >> 4;   // m: ty*8

    const int a_row = tid >> 3;          // 0..31
    const int a_col4 = (tid & 7) * 4;    // 0..28
    const int b_row = tid >> 4;          // 0..15
    const int b_col4 = (tid & 15) * 4;   // 0..60

    float acc[8][4];
#pragma unroll
    for (int i = 0; i < 8; i++)
#pragma unroll
        for (int jj = 0; jj < 4; jj++) acc[i][jj] = 0.f;

    for (int k0 = 0; k0 < K; k0 += BK) {
        // A tile: 128 rows x 32 cols, 4 passes of 32 rows
#pragma unroll
        for (int p = 0; p < 4; p++) {
            int r = block_m + a_row + p * 32;
            float4 v = make_float4(0.f, 0.f, 0.f, 0.f);
            if (r < M)
                v = *reinterpret_cast<const float4*>(A + (size_t)r * K + k0 + a_col4);
            int m = a_row + p * 32;
            As[a_col4 + 0][m] = v.x;
            As[a_col4 + 1][m] = v.y;
            As[a_col4 + 2][m] = v.z;
            As[a_col4 + 3][m] = v.w;
        }
        // B tile: 32 rows x 64 cols, 2 passes of 16 rows
#pragma unroll
        for (int p = 0; p < 2; p++) {
            int r = k0 + b_row + p * 16;
            float4 v = *reinterpret_cast<const float4*>(B + (size_t)r * N + block_n + b_col4);
            *reinterpret_cast<float4*>(&Bs[b_row + p * 16][b_col4]) = v;
        }
        __syncthreads();

#pragma unroll
        for (int kk = 0; kk < BK; kk++) {
            float4 a0 = *reinterpret_cast<const float4*>(&As[kk][ty * 8]);
            float4 a1 = *reinterpret_cast<const float4*>(&As[kk][ty * 8 + 4]);
            float4 b4 = *reinterpret_cast<const float4*>(&Bs[kk][tx * 4]);
            float a[8] = {a0.x, a0.y, a0.z, a0.w, a1.x, a1.y, a1.z, a1.w};
            float b[4] = {b4.x, b4.y, b4.z, b4.w};
#pragma unroll
            for (int i = 0; i < 8; i++)
#pragma unroll
                for (int jj = 0; jj < 4; jj++) acc[i][jj] = fmaf(a[i], b[jj], acc[i][jj]);
        }
        __syncthreads();
    }

#pragma unroll
    for (int i = 0; i < 8; i++) {
        int row = block_m + ty * 8 + i;
        if (row < M) {
            float s = rsC ? __ldg(&rsC[row]) : 1.0f;
            float4 o = make_float4(acc[i][0] * s, acc[i][1] * s, acc[i][2] * s, acc[i][3] * s);
            *reinterpret_cast<float4*>(C + (size_t)row * N + block_n + tx * 4) = o;
        }
    }
}

// ---------------- launch ----------------
extern "C" void kernel_launch(void* const* d_in, const int* in_sizes, int n_in,
                              void* d_out, int out_size) {
    const float* features = (const float*)d_in[0];  // [N, 512]
    const void* src = d_in[1];                      // [E] int32 (int64 hedge via probe)
    const void* dst = d_in[2];                      // [E]
    const float* W1 = (const float*)d_in[3];        // [512, 64]
    const float* W2 = (const float*)d_in[4];        // [64, 512]
    float* out = (float*)d_out;                     // [N, 512]

    const int N = N_NODES;
    const int E = in_sizes[1];

    float *p_x1s, *p_hs, *p_agg2, *p_ns;
    cudaGetSymbolAddress((void**)&p_x1s, g_x1s);
    cudaGetSymbolAddress((void**)&p_hs, g_hs);
    cudaGetSymbolAddress((void**)&p_agg2, g_agg2);
    cudaGetSymbolAddress((void**)&p_ns, g_norm_src);

    const int nb_scan = (N + 1023) / 1024;

    // graph build + norms
    detect_kernel<<<1, 32>>>((const int*)src, (const int*)dst, E);
    zero_counts_kernel<<<(N + 255) / 256, 256>>>(N);
    hist_kernel<<<(E + 255) / 256, 256>>>(src, dst, E);
    norm_kernel<<<(N + 255) / 256, 256>>>(N);
    scan1_kernel<<<nb_scan, 256>>>(N);
    scan2_kernel<<<1, 32>>>(nb_scan);
    scan3_kernel<<<(N + 255) / 256, 256>>>(N, E);
    fill_kernel<<<(E + 255) / 256, 256>>>(src, dst, E);

    // layer 1: x1s = (X @ W1) * ns ; hs = relu(agg1 * nd) * ns
    {
        dim3 grid(HDIM / BN, (N + BM - 1) / BM);
        sgemm_kernel<<<grid, 256>>>(features, W1, p_x1s, N, HDIM, FDIM, p_ns);
    }
    agg_kernel<0><<<(N + 15) / 16, 256>>>(p_x1s, p_hs, N);

    // layer 2: agg2 = (sum hs[src]) * nd ; out = agg2 @ W2
    agg_kernel<1><<<(N + 15) / 16, 256>>>(p_hs, p_agg2, N);
    {
        dim3 grid(FDIM / BN, (N + BM - 1) / BM);
        sgemm_kernel<<<grid, 256>>>(p_agg2, W2, out, N, FDIM, HDIM, nullptr);
    }
}

// round 8
// speedup vs baseline: 2.4031x; 1.2632x over previous
#include <cuda_runtime.h>
#include <cuda_bf16.h>
#include <cstdint>

#define N_NODES 100000
#define E_MAX   1600000
#define FDIM 512
#define HDIM 64

// ---------------- scratch ----------------
__device__ __align__(128) float g_x1s[(size_t)N_NODES * HDIM];   // (X@W1)*ns
__device__ __align__(128) float g_hs[(size_t)N_NODES * HDIM];    // relu(agg1*nd)*ns
__device__ __align__(128) float g_agg2[(size_t)N_NODES * HDIM];  // (agg2*nd)
__device__ __align__(128) float g_norm_src[N_NODES];
__device__ __align__(128) float g_norm_dst[N_NODES];
__device__ int g_cnt_in[N_NODES];
__device__ int g_cnt_out[N_NODES];
__device__ int g_row_start[N_NODES + 1];
__device__ int g_cursor[N_NODES];
__device__ int g_esrc[E_MAX];
__device__ int g_bsum[256];
__device__ int g_is64;

// ---------------- helpers ----------------
__device__ __forceinline__ uint32_t smem_to_u32(const void* p) {
    uint32_t a;
    asm("{ .reg .u64 t; cvta.to.shared.u64 t, %1; cvt.u32.u64 %0, t; }" : "=r"(a) : "l"(p));
    return a;
}
__device__ __forceinline__ void ldsm4(uint32_t* r, uint32_t addr) {
    asm volatile("ldmatrix.sync.aligned.m8n8.x4.shared.b16 {%0,%1,%2,%3}, [%4];"
                 : "=r"(r[0]), "=r"(r[1]), "=r"(r[2]), "=r"(r[3]) : "r"(addr));
}
__device__ __forceinline__ void mma_bf16(float* c, const uint32_t* a, const uint32_t* b) {
    asm volatile(
        "mma.sync.aligned.m16n8k16.row.col.f32.bf16.bf16.f32 "
        "{%0,%1,%2,%3}, {%4,%5,%6,%7}, {%8,%9}, {%0,%1,%2,%3};"
        : "+f"(c[0]), "+f"(c[1]), "+f"(c[2]), "+f"(c[3])
        : "r"(a[0]), "r"(a[1]), "r"(a[2]), "r"(a[3]), "r"(b[0]), "r"(b[1]));
}
__device__ __forceinline__ void bf16split(float x, unsigned short& h, unsigned short& l) {
    __nv_bfloat16 bh = __float2bfloat16(x);
    float fh = __bfloat162float(bh);
    __nv_bfloat16 bl = __float2bfloat16(x - fh);
    h = __bfloat16_as_ushort(bh);
    l = __bfloat16_as_ushort(bl);
}

// ---------------- index width probe ----------------
__global__ void detect_kernel(const int* __restrict__ src32,
                              const int* __restrict__ dst32, int E) {
    if (threadIdx.x == 0 && blockIdx.x == 0) {
        int n = E < 256 ? E : 256;
        int is64 = 1;
        for (int i = 0; i < n; i++) {
            if (src32[2 * i + 1] != 0 || dst32[2 * i + 1] != 0) { is64 = 0; break; }
        }
        g_is64 = is64;
    }
}
__device__ __forceinline__ int load_idx(const void* p, int e, int is64) {
    if (is64) return (int)__ldg(reinterpret_cast<const long long*>(p) + e);
    return __ldg(reinterpret_cast<const int*>(p) + e);
}

// ---------------- graph build ----------------
__global__ __launch_bounds__(256) void zero_counts_kernel(int n) {
    int i = blockIdx.x * blockDim.x + threadIdx.x;
    if (i < n) { g_cnt_in[i] = 0; g_cnt_out[i] = 0; }
}
__global__ __launch_bounds__(256) void hist_kernel(const void* __restrict__ src,
                                                   const void* __restrict__ dst, int E) {
    int e = blockIdx.x * blockDim.x + threadIdx.x;
    if (e < E) {
        int is64 = g_is64;
        atomicAdd(&g_cnt_out[load_idx(src, e, is64)], 1);
        atomicAdd(&g_cnt_in[load_idx(dst, e, is64)], 1);
    }
}
__global__ __launch_bounds__(256) void norm_kernel(int n) {
    int i = blockIdx.x * blockDim.x + threadIdx.x;
    if (i < n) {
        g_norm_src[i] = rsqrtf(fmaxf((float)g_cnt_out[i], 1.0f));
        g_norm_dst[i] = rsqrtf(fmaxf((float)g_cnt_in[i], 1.0f));
    }
}
__global__ __launch_bounds__(256) void scan1_kernel(int n) {
    __shared__ int sh[256];
    int tid = threadIdx.x;
    int base = blockIdx.x * 1024 + tid * 4;
    int v[4];
#pragma unroll
    for (int k = 0; k < 4; k++) v[k] = (base + k < n) ? g_cnt_in[base + k] : 0;
    int t = v[0] + v[1] + v[2] + v[3];
    sh[tid] = t;
    __syncthreads();
    for (int off = 1; off < 256; off <<= 1) {
        int x = (tid >= off) ? sh[tid - off] : 0;
        __syncthreads();
        sh[tid] += x;
        __syncthreads();
    }
    int run = sh[tid] - t;
#pragma unroll
    for (int k = 0; k < 4; k++) {
        if (base + k < n) g_row_start[base + k] = run;
        run += v[k];
    }
    if (tid == 255) g_bsum[blockIdx.x] = sh[255];
}
__global__ void scan2_kernel(int nb) {
    if (threadIdx.x == 0 && blockIdx.x == 0) {
        int running = 0;
        for (int b = 0; b < nb; b++) { int t = g_bsum[b]; g_bsum[b] = running; running += t; }
    }
}
__global__ __launch_bounds__(256) void scan3_kernel(int n, int E) {
    int i = blockIdx.x * blockDim.x + threadIdx.x;
    if (i < n) {
        int v = g_row_start[i] + g_bsum[i >> 10];
        g_row_start[i] = v;
        g_cursor[i] = v;
    }
    if (i == 0) g_row_start[n] = E;
}
__global__ __launch_bounds__(256) void fill_kernel(const void* __restrict__ src,
                                                   const void* __restrict__ dst, int E) {
    int e = blockIdx.x * blockDim.x + threadIdx.x;
    if (e < E) {
        int is64 = g_is64;
        int s = load_idx(src, e, is64);
        int d = load_idx(dst, e, is64);
        int pos = atomicAdd(&g_cursor[d], 1);
        g_esrc[pos] = s;
    }
}

// ---------------- aggregation (CSR, atomic-free) ----------------
template <int MODE>
__global__ __launch_bounds__(256) void agg_kernel(const float* __restrict__ msg,
                                                  float* __restrict__ outbuf, int n) {
    int node = blockIdx.x * 16 + (threadIdx.x >> 4);
    int c = threadIdx.x & 15;
    if (node >= n) return;
    int j = g_row_start[node];
    int s1 = g_row_start[node + 1];
    float4 acc = make_float4(0.f, 0.f, 0.f, 0.f);
    for (; j + 1 < s1; j += 2) {
        int sa = __ldg(&g_esrc[j]);
        int sb = __ldg(&g_esrc[j + 1]);
        float4 va = __ldg(reinterpret_cast<const float4*>(msg + (size_t)sa * HDIM + c * 4));
        float4 vb = __ldg(reinterpret_cast<const float4*>(msg + (size_t)sb * HDIM + c * 4));
        acc.x += va.x; acc.y += va.y; acc.z += va.z; acc.w += va.w;
        acc.x += vb.x; acc.y += vb.y; acc.z += vb.z; acc.w += vb.w;
    }
    if (j < s1) {
        int sa = __ldg(&g_esrc[j]);
        float4 va = __ldg(reinterpret_cast<const float4*>(msg + (size_t)sa * HDIM + c * 4));
        acc.x += va.x; acc.y += va.y; acc.z += va.z; acc.w += va.w;
    }
    float nd = g_norm_dst[node];
    float4 o;
    if (MODE == 0) {
        float ns = g_norm_src[node];
        o.x = fmaxf(acc.x * nd, 0.f) * ns;
        o.y = fmaxf(acc.y * nd, 0.f) * ns;
        o.z = fmaxf(acc.z * nd, 0.f) * ns;
        o.w = fmaxf(acc.w * nd, 0.f) * ns;
    } else {
        o.x = acc.x * nd; o.y = acc.y * nd; o.z = acc.z * nd; o.w = acc.w * nd;
    }
    reinterpret_cast<float4*>(outbuf)[(size_t)node * 16 + c] = o;
}

// ---------------- HMMA bf16-split GEMM ----------------
// C[M, N_total] = A[M, K] @ Wm[K, N_total]; optional row scale rsC.
// CTA tile 128(M) x 64(N), 8 warps as 4(M) x 2(N), warp tile 32x32.
// K chunks of 32. 3 bf16 passes per product: AhBh + AhBl + AlBh (fp32 accum).
// SMEM rows padded to 40 bf16 (80B) -> conflict-free ldmatrix.
#define AST 40
__global__ __launch_bounds__(256) void hmma_gemm_kernel(const float* __restrict__ A,
                                                        const float* __restrict__ Wm,
                                                        float* __restrict__ C,
                                                        int M, int K, int N_total,
                                                        const float* __restrict__ rsC) {
    __shared__ __align__(16) unsigned short sAh[128 * AST];
    __shared__ __align__(16) unsigned short sAl[128 * AST];
    __shared__ __align__(16) unsigned short sBh[64 * AST];
    __shared__ __align__(16) unsigned short sBl[64 * AST];

    const int tid = threadIdx.x;
    const int wid = tid >> 5, lid = tid & 31;
    const int wm = wid & 3, wn = wid >> 2;  // 4(M) x 2(N)
    const int block_m = blockIdx.x * 128;
    const int n0 = blockIdx.y * 64;

    float acc[2][4][4];
#pragma unroll
    for (int i = 0; i < 2; i++)
#pragma unroll
        for (int j = 0; j < 4; j++)
#pragma unroll
            for (int q = 0; q < 4; q++) acc[i][j][q] = 0.f;

    const uint32_t aH = smem_to_u32(sAh);
    const uint32_t aL = smem_to_u32(sAl);
    const uint32_t bH = smem_to_u32(sBh);
    const uint32_t bL = smem_to_u32(sBl);

    for (int k0 = 0; k0 < K; k0 += 32) {
        // ---- A tile: 128 x 32 fp32 -> hi/lo bf16 SMEM [m][k] ----
#pragma unroll
        for (int it = 0; it < 4; it++) {
            int f = it * 256 + tid;     // float4 index (1024 total)
            int r = f >> 3, c4 = f & 7;
            int gr = block_m + r;
            float4 v = make_float4(0.f, 0.f, 0.f, 0.f);
            if (gr < M)
                v = __ldg(reinterpret_cast<const float4*>(A + (size_t)gr * K + k0 + c4 * 4));
            float fv[4] = {v.x, v.y, v.z, v.w};
            unsigned short h[4], l[4];
#pragma unroll
            for (int q = 0; q < 4; q++) bf16split(fv[q], h[q], l[q]);
            uint2 uh = make_uint2((uint32_t)h[0] | ((uint32_t)h[1] << 16),
                                  (uint32_t)h[2] | ((uint32_t)h[3] << 16));
            uint2 ul = make_uint2((uint32_t)l[0] | ((uint32_t)l[1] << 16),
                                  (uint32_t)l[2] | ((uint32_t)l[3] << 16));
            *reinterpret_cast<uint2*>(&sAh[r * AST + c4 * 4]) = uh;
            *reinterpret_cast<uint2*>(&sAl[r * AST + c4 * 4]) = ul;
        }
        // ---- B tile: 32 x 64 fp32 -> hi/lo bf16 SMEM [n][k] (transpose) ----
#pragma unroll
        for (int it = 0; it < 8; it++) {
            int idx = it * 256 + tid;   // 2048 elements
            int kk = idx >> 6, n = idx & 63;
            float w = __ldg(Wm + (size_t)(k0 + kk) * N_total + n0 + n);
            unsigned short h, l;
            bf16split(w, h, l);
            sBh[n * AST + kk] = h;
            sBl[n * AST + kk] = l;
        }
        __syncthreads();

#pragma unroll
        for (int ks = 0; ks < 32; ks += 16) {
            uint32_t ah[2][4], al[2][4], bh[4][2], bl[4][2];
            // A fragments (m16n8k16 a-frag via ldmatrix.x4)
#pragma unroll
            for (int mf = 0; mf < 2; mf++) {
                uint32_t rowA = wm * 32 + mf * 16 + (lid & 15);
                uint32_t off = (rowA * AST + ks + (lid >> 4) * 8) * 2;
                ldsm4(ah[mf], aH + off);
                ldsm4(al[mf], aL + off);
            }
            // B fragments: one x4 covers two n8 frags (n16 x k16)
#pragma unroll
            for (int p = 0; p < 2; p++) {
                uint32_t nrow = wn * 32 + p * 16 + ((lid >> 4) & 1) * 8 + (lid & 7);
                uint32_t off = (nrow * AST + ks + ((lid >> 3) & 1) * 8) * 2;
                uint32_t r[4];
                ldsm4(r, bH + off);
                bh[2 * p][0] = r[0]; bh[2 * p][1] = r[1];
                bh[2 * p + 1][0] = r[2]; bh[2 * p + 1][1] = r[3];
                ldsm4(r, bL + off);
                bl[2 * p][0] = r[0]; bl[2 * p][1] = r[1];
                bl[2 * p + 1][0] = r[2]; bl[2 * p + 1][1] = r[3];
            }
            // 3-pass MMA
#pragma unroll
            for (int mf = 0; mf < 2; mf++)
#pragma unroll
                for (int nf = 0; nf < 4; nf++) {
                    mma_bf16(acc[mf][nf], ah[mf], bh[nf]);
                    mma_bf16(acc[mf][nf], ah[mf], bl[nf]);
                    mma_bf16(acc[mf][nf], al[mf], bh[nf]);
                }
        }
        __syncthreads();
    }

    // ---- epilogue ----
    int lrow = lid >> 2;
    int lcol = (lid & 3) * 2;
#pragma unroll
    for (int mf = 0; mf < 2; mf++) {
#pragma unroll
        for (int half = 0; half < 2; half++) {
            int row = block_m + wm * 32 + mf * 16 + lrow + half * 8;
            if (row < M) {
                float s = rsC ? __ldg(&rsC[row]) : 1.0f;
#pragma unroll
                for (int nf = 0; nf < 4; nf++) {
                    int col = n0 + wn * 32 + nf * 8 + lcol;
                    float2 o = make_float2(acc[mf][nf][half * 2] * s,
                                           acc[mf][nf][half * 2 + 1] * s);
                    *reinterpret_cast<float2*>(C + (size_t)row * N_total + col) = o;
                }
            }
        }
    }
}

// ---------------- launch ----------------
extern "C" void kernel_launch(void* const* d_in, const int* in_sizes, int n_in,
                              void* d_out, int out_size) {
    const float* features = (const float*)d_in[0];  // [N, 512]
    const void* src = d_in[1];
    const void* dst = d_in[2];
    const float* W1 = (const float*)d_in[3];        // [512, 64]
    const float* W2 = (const float*)d_in[4];        // [64, 512]
    float* out = (float*)d_out;                     // [N, 512]

    const int N = N_NODES;
    const int E = in_sizes[1];

    float *p_x1s, *p_hs, *p_agg2, *p_ns;
    cudaGetSymbolAddress((void**)&p_x1s, g_x1s);
    cudaGetSymbolAddress((void**)&p_hs, g_hs);
    cudaGetSymbolAddress((void**)&p_agg2, g_agg2);
    cudaGetSymbolAddress((void**)&p_ns, g_norm_src);

    const int nb_scan = (N + 1023) / 1024;

    detect_kernel<<<1, 32>>>((const int*)src, (const int*)dst, E);
    zero_counts_kernel<<<(N + 255) / 256, 256>>>(N);
    hist_kernel<<<(E + 255) / 256, 256>>>(src, dst, E);
    norm_kernel<<<(N + 255) / 256, 256>>>(N);
    scan1_kernel<<<nb_scan, 256>>>(N);
    scan2_kernel<<<1, 32>>>(nb_scan);
    scan3_kernel<<<(N + 255) / 256, 256>>>(N, E);
    fill_kernel<<<(E + 255) / 256, 256>>>(src, dst, E);

    const int mtiles = (N + 127) / 128;
    // layer 1: x1s = (X @ W1) * ns
    {
        dim3 grid(mtiles, 1);
        hmma_gemm_kernel<<<grid, 256>>>(features, W1, p_x1s, N, FDIM, HDIM, p_ns);
    }
    agg_kernel<0><<<(N + 15) / 16, 256>>>(p_x1s, p_hs, N);
    // layer 2
    agg_kernel<1><<<(N + 15) / 16, 256>>>(p_hs, p_agg2, N);
    {
        dim3 grid(mtiles, FDIM / 64);
        hmma_gemm_kernel<<<grid, 256>>>(p_agg2, W2, out, N, HDIM, FDIM, nullptr);
    }
}